// round 12
// baseline (speedup 1.0000x reference)
#include <cuda_runtime.h>
#include <cstdint>

#define N_IMG 32
#define C_IN  128
#define H_DIM 56
#define W_DIM 56
#define P_OUT 128
#define HP (H_DIM + 2)
#define WP (W_DIM + 2)
#define BN_EPS 1e-5f
#define NA_BLOCKS (N_IMG * 15)        // pack_a blocks in the fused pack kernel

// Scratch (allocation-free rule: __device__ globals)
__device__ uint4  g_apack[N_IMG * HP * WP];   // packed activations, zero border
__device__ uint4  g_wpack[P_OUT * 9];         // packed weights per tap (4 x u32)
__device__ int    g_corr[P_OUT * 8];          // border-correction values per out-channel
__device__ float2 g_sc[P_OUT];                // (scale, offset) fused bias+BN

// full adder: sum of three bit-vectors -> sum (w1) + carry (w2). 2 LOP3s.
__device__ __forceinline__ void fa(unsigned a, unsigned b, unsigned c,
                                   unsigned &s, unsigned &cy) {
    s  = a ^ b ^ c;                       // LOP3 0x96
    cy = (a & b) | (a & c) | (b & c);     // LOP3 0xE8 (majority)
}

// 9-input CSA popcount: taps t[0..8] -> weighted popc partials (4 POPC).
__device__ __forceinline__ void popc9(const unsigned* t, int &p1, int &p2, int &p4) {
    unsigned s1a, c1a, s1b, c1b, s1c, c1c;
    fa(t[0], t[1], t[2], s1a, c1a);
    fa(t[3], t[4], t[5], s1b, c1b);
    fa(t[6], t[7], t[8], s1c, c1c);
    unsigned S1, C2a, S2, C4;
    fa(s1a, s1b, s1c, S1, C2a);     // weight 1 + weight 2
    fa(c1a, c1b, c1c, S2, C4);      // weight 2 + weight 4
    p1 += __popc(S1);
    p2 += __popc(C2a) + __popc(S2);
    p4 += __popc(C4);
}

// ---------------------------------------------------------------------------
// Fused pack kernel: blocks [0, NA_BLOCKS) pack activations, blocks
// [NA_BLOCKS, NA_BLOCKS+128) pack weights + corrections + BN constants.
// ---------------------------------------------------------------------------
__global__ void __launch_bounds__(256)
pack_kernel(const float* __restrict__ x,
            const float* __restrict__ w,
            const float* __restrict__ bias,
            const float* __restrict__ gamma,
            const float* __restrict__ beta,
            const float* __restrict__ rmean,
            const float* __restrict__ rvar) {
    if (blockIdx.x < NA_BLOCKS) {
        // ---- pack activations: 1-pixel zero border, 4 padded rows per block
        int b = blockIdx.x;
        int rq = b % 15;
        int n  = b / 15;
        int hp = rq * 4 + (threadIdx.x >> 6);
        int wp = threadIdx.x & 63;
        if (hp >= HP || wp >= WP) return;

        uint4 v = make_uint4(0u, 0u, 0u, 0u);
        if (hp >= 1 && hp <= H_DIM && wp >= 1 && wp <= W_DIM) {
            int h = hp - 1, ww = wp - 1;
            const float* base = x + (size_t)n * C_IN * H_DIM * W_DIM + h * W_DIM + ww;
            unsigned int words[4] = {0u, 0u, 0u, 0u};
            #pragma unroll 8
            for (int c = 0; c < C_IN; c++) {
                float f = base[(size_t)c * H_DIM * W_DIM];
                words[c >> 5] |= (unsigned int)(f >= 0.0f) << (c & 31);
            }
            v = make_uint4(words[0], words[1], words[2], words[3]);
        }
        g_apack[(n * HP + hp) * WP + wp] = v;
    } else {
        // ---- pack weights: one block per output channel
        int p = blockIdx.x - NA_BLOCKS;   // 0..127
        int c = threadIdx.x;              // 0..255; only c<128 contribute ballots
        int lane = c & 31, wd = c >> 5;

        __shared__ unsigned sw[9][4];
        __shared__ int ssum[9];

        if (c < 128) {
            #pragma unroll
            for (int t = 0; t < 9; t++) {
                float v = w[(size_t)(p * C_IN + c) * 9 + t];
                unsigned m = __ballot_sync(0xffffffffu, v >= 0.0f);
                if (lane == 0) sw[t][wd] = m;
            }
        }
        __syncthreads();

        if (c < 9) {
            int t = c;
            int pc = __popc(sw[t][0]) + __popc(sw[t][1]) + __popc(sw[t][2]) + __popc(sw[t][3]);
            ssum[t] = 2 * pc - C_IN;
        }
        __syncthreads();

        if (c < 9) {
            g_wpack[p * 9 + c] = make_uint4(sw[c][0], sw[c][1], sw[c][2], sw[c][3]);
        }
        if (c == 0) {
            const int* ws = ssum;
            g_corr[p * 8 + 0] = ws[0] + ws[1] + ws[2];   // top row
            g_corr[p * 8 + 1] = ws[6] + ws[7] + ws[8];   // bottom row
            g_corr[p * 8 + 2] = ws[0] + ws[3] + ws[6];   // left col
            g_corr[p * 8 + 3] = ws[2] + ws[5] + ws[8];   // right col
            g_corr[p * 8 + 4] = ws[0];                   // corners
            g_corr[p * 8 + 5] = ws[2];
            g_corr[p * 8 + 6] = ws[6];
            g_corr[p * 8 + 7] = ws[8];

            float inv = gamma[p] / sqrtf(rvar[p] + BN_EPS);
            float offs = bias[p] * inv + beta[p] - rmean[p] * inv;
            g_sc[p] = make_float2(inv, offs);
        }
    }
}

// ---------------------------------------------------------------------------
// Fused XNOR conv + bias + BN + residual. Zero-idle-lane geometry (224 thr,
// jr = t/56 row pair, w = t%56 column, one 32-channel group per block).
// This round: min-3-CTAs-per-SM register budget (96) + channel-loop unroll 1
// to raise occupancy 18.5% -> ~28% and close the 25% alu-pipe idle gap.
// ---------------------------------------------------------------------------
__global__ void __launch_bounds__(224, 3)
conv_kernel(const float* __restrict__ x, float* __restrict__ out) {
    __shared__ uint4  s_act[10 * WP];     // 9.3 KB (padded rows hp0..hp0+9)
    __shared__ uint4  s_w[32 * 9];        // 4.6 KB (this block's channel group)
    __shared__ int    s_corr[32 * 8];     // 1 KB
    __shared__ float2 s_sc[32];

    int b = blockIdx.x;                   // ((n*7 + rq)*4 + cg)
    int cg = b & 3;
    int rq = (b >> 2) % 7;
    int n  = b / 28;
    int cbase = cg * 32;
    int t = threadIdx.x;

    for (int i = t; i < 32 * 9; i += 224) s_w[i] = g_wpack[cbase * 9 + i];
    for (int i = t; i < 32 * 8; i += 224) s_corr[i] = g_corr[cbase * 8 + i];
    if (t < 32) s_sc[t] = g_sc[cbase + t];
    int hp0 = rq * 8;
    for (int i = t; i < 10 * WP; i += 224)
        s_act[i] = g_apack[(n * HP + hp0 + i / WP) * WP + (i % WP)];
    __syncthreads();

    int jr = t / 56;                      // row pair within tile: 0..3
    int w  = t % 56;                      // column: 0..55
    int h0 = hp0 + jr * 2;                // output row (even, 0..54)

    // 4 rows x 3 cols of packed activations in registers: xa[row][col*4+u]
    unsigned xa[4][12];
    #pragma unroll
    for (int dr = 0; dr < 4; dr++) {
        #pragma unroll
        for (int dc = 0; dc < 3; dc++) {
            uint4 v = s_act[(jr * 2 + dr) * WP + w + dc];
            xa[dr][dc * 4 + 0] = v.x; xa[dr][dc * 4 + 1] = v.y;
            xa[dr][dc * 4 + 2] = v.z; xa[dr][dc * 4 + 3] = v.w;
        }
    }

    // border flags (h0 even: never bottom; h0+1 odd >= 1: never top)
    int ft0 = (h0 == 0), fb1 = (h0 + 1 == H_DIM - 1);
    int fl = (w == 0), fr = (w == W_DIM - 1);

    const size_t cstride = (size_t)H_DIM * W_DIM;
    const float* xin0 = x   + ((size_t)(n * P_OUT + cbase) * H_DIM + h0) * W_DIM + w;
    float*       ob0  = out + ((size_t)(n * P_OUT + cbase) * H_DIM + h0) * W_DIM + w;

    #pragma unroll 1
    for (int i = 0; i < 32; i++) {
        // load 9 weight vectors (warp-uniform -> broadcast LDS.128)
        unsigned wv[9][4];
        #pragma unroll
        for (int tp = 0; tp < 9; tp++) {
            uint4 v = s_w[i * 9 + tp];
            wv[tp][0] = v.x; wv[tp][1] = v.y; wv[tp][2] = v.z; wv[tp][3] = v.w;
        }

        int p1a = 0, p2a = 0, p4a = 0;   // row h0
        int p1b = 0, p2b = 0, p4b = 0;   // row h0+1
        #pragma unroll
        for (int u = 0; u < 4; u++) {
            unsigned ta[9], tb[9];
            #pragma unroll
            for (int tp = 0; tp < 9; tp++) {
                int dr = tp / 3, dc = tp % 3;
                ta[tp] = xa[dr    ][dc * 4 + u] ^ wv[tp][u];
                tb[tp] = xa[dr + 1][dc * 4 + u] ^ wv[tp][u];
            }
            popc9(ta, p1a, p2a, p4a);
            popc9(tb, p1b, p2b, p4b);
        }
        int dot0 = 9 * C_IN - 2 * (p1a + 2 * p2a + 4 * p4a);
        int dot1 = 9 * C_IN - 2 * (p1b + 2 * p2b + 4 * p4b);

        const int* cr = &s_corr[i * 8];
        dot0 += ft0 * cr[0] + fl * cr[2] + fr * cr[3]
              - (ft0 & fl) * cr[4] - (ft0 & fr) * cr[5];
        dot1 += fb1 * cr[1] + fl * cr[2] + fr * cr[3]
              - (fb1 & fl) * cr[6] - (fb1 & fr) * cr[7];

        float2 sc = s_sc[i];
        ob0[i * cstride]         = (float)dot0 * sc.x + sc.y + xin0[i * cstride];
        ob0[i * cstride + W_DIM] = (float)dot1 * sc.x + sc.y + xin0[i * cstride + W_DIM];
    }
}

// ---------------------------------------------------------------------------
extern "C" void kernel_launch(void* const* d_in, const int* in_sizes, int n_in,
                              void* d_out, int out_size) {
    const float* x     = (const float*)d_in[0];
    const float* w     = (const float*)d_in[1];
    const float* bias  = (const float*)d_in[2];
    const float* gamma = (const float*)d_in[3];
    const float* beta  = (const float*)d_in[4];
    const float* rmean = (const float*)d_in[5];
    const float* rvar  = (const float*)d_in[6];
    float* out = (float*)d_out;

    pack_kernel<<<NA_BLOCKS + P_OUT, 256>>>(x, w, bias, gamma, beta, rmean, rvar);
    conv_kernel<<<N_IMG * 7 * 4, 224>>>(x, out);
}

// round 13
// speedup vs baseline: 1.2164x; 1.2164x over previous
#include <cuda_runtime.h>
#include <cstdint>

#define N_IMG 32
#define C_IN  128
#define H_DIM 56
#define W_DIM 56
#define P_OUT 128
#define HP (H_DIM + 2)
#define WP (W_DIM + 2)
#define BN_EPS 1e-5f
#define NA_BLOCKS (N_IMG * 15)        // pack_a blocks in the fused pack kernel

// Scratch (allocation-free rule: __device__ globals)
__device__ uint4  g_apack[N_IMG * HP * WP];   // packed activations, zero border
__device__ uint4  g_wpack[P_OUT * 9];         // packed weights per tap (4 x u32)
__device__ int    g_corr[P_OUT * 8];          // border-correction values per out-channel
__device__ float2 g_sc[P_OUT];                // (scale, offset) fused bias+BN

// full adder: sum of three bit-vectors -> sum (w1) + carry (w2). 2 LOP3s.
__device__ __forceinline__ void fa(unsigned a, unsigned b, unsigned c,
                                   unsigned &s, unsigned &cy) {
    s  = a ^ b ^ c;                       // LOP3 0x96
    cy = (a & b) | (a & c) | (b & c);     // LOP3 0xE8 (majority)
}

// 9-input CSA popcount: taps t[0..8] -> weighted popc partials (4 POPC).
__device__ __forceinline__ void popc9(const unsigned* t, int &p1, int &p2, int &p4) {
    unsigned s1a, c1a, s1b, c1b, s1c, c1c;
    fa(t[0], t[1], t[2], s1a, c1a);
    fa(t[3], t[4], t[5], s1b, c1b);
    fa(t[6], t[7], t[8], s1c, c1c);
    unsigned S1, C2a, S2, C4;
    fa(s1a, s1b, s1c, S1, C2a);     // weight 1 + weight 2
    fa(c1a, c1b, c1c, S2, C4);      // weight 2 + weight 4
    p1 += __popc(S1);
    p2 += __popc(C2a) + __popc(S2);
    p4 += __popc(C4);
}

// ---------------------------------------------------------------------------
// Fused pack kernel: blocks [0, NA_BLOCKS) pack activations, blocks
// [NA_BLOCKS, NA_BLOCKS+128) pack weights + corrections + BN constants.
// ---------------------------------------------------------------------------
__global__ void __launch_bounds__(256)
pack_kernel(const float* __restrict__ x,
            const float* __restrict__ w,
            const float* __restrict__ bias,
            const float* __restrict__ gamma,
            const float* __restrict__ beta,
            const float* __restrict__ rmean,
            const float* __restrict__ rvar) {
    if (blockIdx.x < NA_BLOCKS) {
        int b = blockIdx.x;
        int rq = b % 15;
        int n  = b / 15;
        int hp = rq * 4 + (threadIdx.x >> 6);
        int wp = threadIdx.x & 63;
        if (hp >= HP || wp >= WP) return;

        uint4 v = make_uint4(0u, 0u, 0u, 0u);
        if (hp >= 1 && hp <= H_DIM && wp >= 1 && wp <= W_DIM) {
            int h = hp - 1, ww = wp - 1;
            const float* base = x + (size_t)n * C_IN * H_DIM * W_DIM + h * W_DIM + ww;
            unsigned int words[4] = {0u, 0u, 0u, 0u};
            #pragma unroll 8
            for (int c = 0; c < C_IN; c++) {
                float f = base[(size_t)c * H_DIM * W_DIM];
                words[c >> 5] |= (unsigned int)(f >= 0.0f) << (c & 31);
            }
            v = make_uint4(words[0], words[1], words[2], words[3]);
        }
        g_apack[(n * HP + hp) * WP + wp] = v;
    } else {
        int p = blockIdx.x - NA_BLOCKS;   // 0..127
        int c = threadIdx.x;
        int lane = c & 31, wd = c >> 5;

        __shared__ unsigned sw[9][4];
        __shared__ int ssum[9];

        if (c < 128) {
            #pragma unroll
            for (int t = 0; t < 9; t++) {
                float v = w[(size_t)(p * C_IN + c) * 9 + t];
                unsigned m = __ballot_sync(0xffffffffu, v >= 0.0f);
                if (lane == 0) sw[t][wd] = m;
            }
        }
        __syncthreads();

        if (c < 9) {
            int t = c;
            int pc = __popc(sw[t][0]) + __popc(sw[t][1]) + __popc(sw[t][2]) + __popc(sw[t][3]);
            ssum[t] = 2 * pc - C_IN;
        }
        __syncthreads();

        if (c < 9) {
            g_wpack[p * 9 + c] = make_uint4(sw[c][0], sw[c][1], sw[c][2], sw[c][3]);
        }
        if (c == 0) {
            const int* ws = ssum;
            g_corr[p * 8 + 0] = ws[0] + ws[1] + ws[2];   // top row
            g_corr[p * 8 + 1] = ws[6] + ws[7] + ws[8];   // bottom row
            g_corr[p * 8 + 2] = ws[0] + ws[3] + ws[6];   // left col
            g_corr[p * 8 + 3] = ws[2] + ws[5] + ws[8];   // right col
            g_corr[p * 8 + 4] = ws[0];                   // corners
            g_corr[p * 8 + 5] = ws[2];
            g_corr[p * 8 + 6] = ws[6];
            g_corr[p * 8 + 7] = ws[8];

            float inv = gamma[p] / sqrtf(rvar[p] + BN_EPS);
            float offs = bias[p] * inv + beta[p] - rmean[p] * inv;
            g_sc[p] = make_float2(inv, offs);
        }
    }
}

// ---------------------------------------------------------------------------
// Fused XNOR conv + bias + BN + residual, K-split across lane pairs.
// 224 threads: uh = t&1 picks a 64-channel half (u-words 2uh, 2uh+1);
// j = t>>1 picks (column w = j%56, row-pair rp = j/56). Each thread computes
// both rows' PARTIAL popcounts for its channel-half; one shfl_xor(.,1)
// exchanges cross partials so thread uh finalizes + stores row (h0+uh).
// Natural register need ~85 -> 3 CTAs/SM at launch_bounds(224,3), no spill.
// ---------------------------------------------------------------------------
__global__ void __launch_bounds__(224, 3)
conv_kernel(const float* __restrict__ x, float* __restrict__ out) {
    __shared__ uint4    s_act[6 * WP];     // 5.6 KB (padded rows hp0..hp0+5)
    __shared__ unsigned s_wt[32 * 40];     // 5 KB: [ch][uh(20-word half)][tap*2+u2]
    __shared__ int      s_corr[32 * 8];    // 1 KB
    __shared__ float2   s_sc[32];

    int b = blockIdx.x;                    // ((n*14 + rblk)*4 + cg)
    int cg   = b & 3;
    int rblk = (b >> 2) % 14;
    int n    = b / 56;
    int cbase = cg * 32;
    int t = threadIdx.x;

    // stage weights re-laid by channel-half: half uh holds words {2uh, 2uh+1}
    for (int idx = t; idx < 32 * 9; idx += 224) {
        int i = idx / 9, tap = idx % 9;
        uint4 v = g_wpack[(cbase + i) * 9 + tap];
        s_wt[i * 40 +      tap * 2 + 0] = v.x;
        s_wt[i * 40 +      tap * 2 + 1] = v.y;
        s_wt[i * 40 + 20 + tap * 2 + 0] = v.z;
        s_wt[i * 40 + 20 + tap * 2 + 1] = v.w;
    }
    for (int i = t; i < 32 * 8; i += 224) s_corr[i] = g_corr[cbase * 8 + i];
    if (t < 32) s_sc[t] = g_sc[cbase + t];
    int hp0 = rblk * 4;
    for (int i = t; i < 6 * WP; i += 224)
        s_act[i] = g_apack[(n * HP + hp0 + i / WP) * WP + (i % WP)];
    __syncthreads();

    int uh = t & 1;           // channel-half (and the row this thread stores)
    int j  = t >> 1;          // 0..111
    int w  = j % 56;
    int rp = j / 56;          // row pair within the 4-row tile
    int h  = hp0 + rp * 2 + uh;   // this thread's output row

    // activation window: 4 rows x 3 cols x 2 words (this channel-half)
    unsigned xa[4][6];
    #pragma unroll
    for (int dr = 0; dr < 4; dr++) {
        #pragma unroll
        for (int dc = 0; dc < 3; dc++) {
            const unsigned* pv = (const unsigned*)&s_act[(rp * 2 + dr) * WP + w + dc];
            xa[dr][dc * 2 + 0] = pv[2 * uh + 0];
            xa[dr][dc * 2 + 1] = pv[2 * uh + 1];
        }
    }

    // border flags for THIS thread's row
    int ft = (h == 0), fb = (h == H_DIM - 1);
    int fl = (w == 0), fr = (w == W_DIM - 1);

    const size_t cstride = (size_t)H_DIM * W_DIM;
    const float* xin = x   + ((size_t)(n * P_OUT + cbase) * H_DIM + h) * W_DIM + w;
    float*       ob  = out + ((size_t)(n * P_OUT + cbase) * H_DIM + h) * W_DIM + w;
    const unsigned* wbase = &s_wt[uh * 20];

    #pragma unroll 1
    for (int i = 0; i < 32; i++) {
        // 18 weight words for this channel & half: 4 x LDS.128 + 1 x LDS.64
        unsigned wv[18];
        {
            const uint4* w4 = (const uint4*)(wbase + i * 40);
            uint4 a0 = w4[0], a1 = w4[1], a2 = w4[2], a3 = w4[3];
            wv[0]=a0.x; wv[1]=a0.y; wv[2]=a0.z;  wv[3]=a0.w;
            wv[4]=a1.x; wv[5]=a1.y; wv[6]=a1.z;  wv[7]=a1.w;
            wv[8]=a2.x; wv[9]=a2.y; wv[10]=a2.z; wv[11]=a2.w;
            wv[12]=a3.x; wv[13]=a3.y; wv[14]=a3.z; wv[15]=a3.w;
            uint2 a4 = *(const uint2*)(wbase + i * 40 + 16);
            wv[16]=a4.x; wv[17]=a4.y;
        }

        int p1a = 0, p2a = 0, p4a = 0;   // pair row 0, this half
        int p1b = 0, p2b = 0, p4b = 0;   // pair row 1, this half
        #pragma unroll
        for (int u2 = 0; u2 < 2; u2++) {
            unsigned ta[9], tb[9];
            #pragma unroll
            for (int tp = 0; tp < 9; tp++) {
                int dr = tp / 3, dc = tp % 3;
                ta[tp] = xa[dr    ][dc * 2 + u2] ^ wv[tp * 2 + u2];
                tb[tp] = xa[dr + 1][dc * 2 + u2] ^ wv[tp * 2 + u2];
            }
            popc9(ta, p1a, p2a, p4a);
            popc9(tb, p1b, p2b, p4b);
        }
        int pc0 = p1a + 2 * p2a + 4 * p4a;
        int pc1 = p1b + 2 * p2b + 4 * p4b;

        // cross-exchange: keep own row's partial, send the other row's.
        int keep = uh ? pc1 : pc0;
        int send = uh ? pc0 : pc1;
        int full = keep + __shfl_xor_sync(0xffffffffu, send, 1);

        int dot = 9 * C_IN - 2 * full;
        const int* cr = &s_corr[i * 8];
        dot += ft * cr[0] + fb * cr[1] + fl * cr[2] + fr * cr[3]
             - (ft & fl) * cr[4] - (ft & fr) * cr[5]
             - (fb & fl) * cr[6] - (fb & fr) * cr[7];

        float2 sc = s_sc[i];
        ob[i * cstride] = (float)dot * sc.x + sc.y + xin[i * cstride];
    }
}

// ---------------------------------------------------------------------------
extern "C" void kernel_launch(void* const* d_in, const int* in_sizes, int n_in,
                              void* d_out, int out_size) {
    const float* x     = (const float*)d_in[0];
    const float* w     = (const float*)d_in[1];
    const float* bias  = (const float*)d_in[2];
    const float* gamma = (const float*)d_in[3];
    const float* beta  = (const float*)d_in[4];
    const float* rmean = (const float*)d_in[5];
    const float* rvar  = (const float*)d_in[6];
    float* out = (float*)d_out;

    pack_kernel<<<NA_BLOCKS + P_OUT, 256>>>(x, w, bias, gamma, beta, rmean, rvar);
    conv_kernel<<<N_IMG * 14 * 4, 224>>>(x, out);
}

// round 14
// speedup vs baseline: 1.2339x; 1.0144x over previous
#include <cuda_runtime.h>
#include <cstdint>

#define N_IMG 32
#define C_IN  128
#define H_DIM 56
#define W_DIM 56
#define P_OUT 128
#define HP (H_DIM + 2)
#define WP (W_DIM + 2)
#define BN_EPS 1e-5f
#define NA_BLOCKS (N_IMG * 15)        // pack_a blocks in the fused pack kernel

// Scratch (allocation-free rule: __device__ globals)
__device__ uint4  g_apack[N_IMG * HP * WP];   // packed activations, zero border
__device__ uint4  g_wpack[P_OUT * 9];         // packed weights per tap (4 x u32)
__device__ int    g_corr[P_OUT * 8];          // border-correction values per out-channel
__device__ float2 g_sc[P_OUT];                // (scale, offset) fused bias+BN

// full adder: sum of three bit-vectors -> sum (w1) + carry (w2). 2 LOP3s.
__device__ __forceinline__ void fa(unsigned a, unsigned b, unsigned c,
                                   unsigned &s, unsigned &cy) {
    s  = a ^ b ^ c;                       // LOP3 0x96
    cy = (a & b) | (a & c) | (b & c);     // LOP3 0xE8 (majority)
}

// 9-input CSA popcount: taps t[0..8] -> weighted popc partials (4 POPC).
__device__ __forceinline__ void popc9(const unsigned* t, int &p1, int &p2, int &p4) {
    unsigned s1a, c1a, s1b, c1b, s1c, c1c;
    fa(t[0], t[1], t[2], s1a, c1a);
    fa(t[3], t[4], t[5], s1b, c1b);
    fa(t[6], t[7], t[8], s1c, c1c);
    unsigned S1, C2a, S2, C4;
    fa(s1a, s1b, s1c, S1, C2a);     // weight 1 + weight 2
    fa(c1a, c1b, c1c, S2, C4);      // weight 2 + weight 4
    p1 += __popc(S1);
    p2 += __popc(C2a) + __popc(S2);
    p4 += __popc(C4);
}

// ---------------------------------------------------------------------------
// Fused pack kernel: blocks [0, NA_BLOCKS) pack activations, blocks
// [NA_BLOCKS, NA_BLOCKS+128) pack weights + corrections + BN constants.
// ---------------------------------------------------------------------------
__global__ void __launch_bounds__(256)
pack_kernel(const float* __restrict__ x,
            const float* __restrict__ w,
            const float* __restrict__ bias,
            const float* __restrict__ gamma,
            const float* __restrict__ beta,
            const float* __restrict__ rmean,
            const float* __restrict__ rvar) {
    if (blockIdx.x < NA_BLOCKS) {
        int b = blockIdx.x;
        int rq = b % 15;
        int n  = b / 15;
        int hp = rq * 4 + (threadIdx.x >> 6);
        int wp = threadIdx.x & 63;
        if (hp >= HP || wp >= WP) return;

        uint4 v = make_uint4(0u, 0u, 0u, 0u);
        if (hp >= 1 && hp <= H_DIM && wp >= 1 && wp <= W_DIM) {
            int h = hp - 1, ww = wp - 1;
            const float* base = x + (size_t)n * C_IN * H_DIM * W_DIM + h * W_DIM + ww;
            unsigned int words[4] = {0u, 0u, 0u, 0u};
            #pragma unroll 8
            for (int c = 0; c < C_IN; c++) {
                float f = base[(size_t)c * H_DIM * W_DIM];
                words[c >> 5] |= (unsigned int)(f >= 0.0f) << (c & 31);
            }
            v = make_uint4(words[0], words[1], words[2], words[3]);
        }
        g_apack[(n * HP + hp) * WP + wp] = v;
    } else {
        int p = blockIdx.x - NA_BLOCKS;   // 0..127
        int c = threadIdx.x;
        int lane = c & 31, wd = c >> 5;

        __shared__ unsigned sw[9][4];
        __shared__ int ssum[9];

        if (c < 128) {
            #pragma unroll
            for (int t = 0; t < 9; t++) {
                float v = w[(size_t)(p * C_IN + c) * 9 + t];
                unsigned m = __ballot_sync(0xffffffffu, v >= 0.0f);
                if (lane == 0) sw[t][wd] = m;
            }
        }
        __syncthreads();

        if (c < 9) {
            int t = c;
            int pc = __popc(sw[t][0]) + __popc(sw[t][1]) + __popc(sw[t][2]) + __popc(sw[t][3]);
            ssum[t] = 2 * pc - C_IN;
        }
        __syncthreads();

        if (c < 9) {
            g_wpack[p * 9 + c] = make_uint4(sw[c][0], sw[c][1], sw[c][2], sw[c][3]);
        }
        if (c == 0) {
            const int* ws = ssum;
            g_corr[p * 8 + 0] = ws[0] + ws[1] + ws[2];   // top row
            g_corr[p * 8 + 1] = ws[6] + ws[7] + ws[8];   // bottom row
            g_corr[p * 8 + 2] = ws[0] + ws[3] + ws[6];   // left col
            g_corr[p * 8 + 3] = ws[2] + ws[5] + ws[8];   // right col
            g_corr[p * 8 + 4] = ws[0];                   // corners
            g_corr[p * 8 + 5] = ws[2];
            g_corr[p * 8 + 6] = ws[6];
            g_corr[p * 8 + 7] = ws[8];

            float inv = gamma[p] / sqrtf(rvar[p] + BN_EPS);
            float offs = bias[p] * inv + beta[p] - rmean[p] * inv;
            g_sc[p] = make_float2(inv, offs);
        }
    }
}

// ---------------------------------------------------------------------------
// Fused XNOR conv + bias + BN + residual, K-split across lane pairs.
// Same geometry as the r13 champion (224 thr, uh = t&1 channel-half,
// shfl_xor partial exchange, 3 CTAs/SM). This round adds:
//   - depth-2 LDG prefetch of the residual x value (hides DRAM latency)
//   - per-u2 weight loads from a [ch][u][tap] smem layout (9 words just
//     before use -> shorter LDS dependency, fewer live registers)
// ---------------------------------------------------------------------------
__global__ void __launch_bounds__(224, 3)
conv_kernel(const float* __restrict__ x, float* __restrict__ out) {
    __shared__ uint4    s_act[6 * WP];     // 5.6 KB (padded rows hp0..hp0+5)
    __shared__ unsigned s_wt[32 * 48];     // 6 KB: [ch][u-word 0..3][tap 0..8, pad 12]
    __shared__ int      s_corr[32 * 8];    // 1 KB
    __shared__ float2   s_sc[32];

    int b = blockIdx.x;                    // ((n*14 + rblk)*4 + cg)
    int cg   = b & 3;
    int rblk = (b >> 2) % 14;
    int n    = b / 56;
    int cbase = cg * 32;
    int t = threadIdx.x;

    // stage weights: s_wt[ch*48 + u*12 + tap] = word u of tap
    for (int idx = t; idx < 32 * 9; idx += 224) {
        int i = idx / 9, tap = idx % 9;
        uint4 v = g_wpack[(cbase + i) * 9 + tap];
        s_wt[i * 48 +  0 + tap] = v.x;
        s_wt[i * 48 + 12 + tap] = v.y;
        s_wt[i * 48 + 24 + tap] = v.z;
        s_wt[i * 48 + 36 + tap] = v.w;
    }
    for (int i = t; i < 32 * 8; i += 224) s_corr[i] = g_corr[cbase * 8 + i];
    if (t < 32) s_sc[t] = g_sc[cbase + t];
    int hp0 = rblk * 4;
    for (int i = t; i < 6 * WP; i += 224)
        s_act[i] = g_apack[(n * HP + hp0 + i / WP) * WP + (i % WP)];
    __syncthreads();

    int uh = t & 1;           // channel-half (and the row this thread stores)
    int j  = t >> 1;          // 0..111
    int w  = j % 56;
    int rp = j / 56;          // row pair within the 4-row tile
    int h  = hp0 + rp * 2 + uh;   // this thread's output row

    // activation window: 4 rows x 3 cols x 2 words (this channel-half)
    unsigned xa[4][6];
    #pragma unroll
    for (int dr = 0; dr < 4; dr++) {
        #pragma unroll
        for (int dc = 0; dc < 3; dc++) {
            const unsigned* pv = (const unsigned*)&s_act[(rp * 2 + dr) * WP + w + dc];
            xa[dr][dc * 2 + 0] = pv[2 * uh + 0];
            xa[dr][dc * 2 + 1] = pv[2 * uh + 1];
        }
    }

    // border flags for THIS thread's row
    int ft = (h == 0), fb = (h == H_DIM - 1);
    int fl = (w == 0), fr = (w == W_DIM - 1);

    const size_t cstride = (size_t)H_DIM * W_DIM;
    const float* xin = x   + ((size_t)(n * P_OUT + cbase) * H_DIM + h) * W_DIM + w;
    float*       ob  = out + ((size_t)(n * P_OUT + cbase) * H_DIM + h) * W_DIM + w;
    const unsigned* wb = &s_wt[uh * 24];   // u2=0 at +0, u2=1 at +12

    // depth-2 residual prefetch pipeline
    float xc = xin[0];
    float x1 = xin[cstride];

    #pragma unroll 1
    for (int i = 0; i < 32; i++) {
        int ipre = (i + 2 < 32) ? (i + 2) : 31;
        float x2 = xin[(size_t)ipre * cstride];

        int p1a = 0, p2a = 0, p4a = 0;   // pair row 0, this half
        int p1b = 0, p2b = 0, p4b = 0;   // pair row 1, this half

        #pragma unroll
        for (int u2 = 0; u2 < 2; u2++) {
            // 9 weight words for (channel i, this half, this u2)
            const unsigned* wp9 = wb + i * 48 + u2 * 12;
            uint4 q0 = *(const uint4*)(wp9);
            uint4 q1 = *(const uint4*)(wp9 + 4);
            unsigned w8 = wp9[8];
            unsigned wv[9] = {q0.x, q0.y, q0.z, q0.w, q1.x, q1.y, q1.z, q1.w, w8};

            unsigned ta[9], tb[9];
            #pragma unroll
            for (int tp = 0; tp < 9; tp++) {
                int dr = tp / 3, dc = tp % 3;
                ta[tp] = xa[dr    ][dc * 2 + u2] ^ wv[tp];
                tb[tp] = xa[dr + 1][dc * 2 + u2] ^ wv[tp];
            }
            popc9(ta, p1a, p2a, p4a);
            popc9(tb, p1b, p2b, p4b);
        }
        int pc0 = p1a + 2 * p2a + 4 * p4a;
        int pc1 = p1b + 2 * p2b + 4 * p4b;

        // cross-exchange: keep own row's partial, send the other row's.
        int keep = uh ? pc1 : pc0;
        int send = uh ? pc0 : pc1;
        int full = keep + __shfl_xor_sync(0xffffffffu, send, 1);

        int dot = 9 * C_IN - 2 * full;
        const int* cr = &s_corr[i * 8];
        dot += ft * cr[0] + fb * cr[1] + fl * cr[2] + fr * cr[3]
             - (ft & fl) * cr[4] - (ft & fr) * cr[5]
             - (fb & fl) * cr[6] - (fb & fr) * cr[7];

        float2 sc = s_sc[i];
        ob[i * cstride] = (float)dot * sc.x + sc.y + xc;
        xc = x1;
        x1 = x2;
    }
}

// ---------------------------------------------------------------------------
extern "C" void kernel_launch(void* const* d_in, const int* in_sizes, int n_in,
                              void* d_out, int out_size) {
    const float* x     = (const float*)d_in[0];
    const float* w     = (const float*)d_in[1];
    const float* bias  = (const float*)d_in[2];
    const float* gamma = (const float*)d_in[3];
    const float* beta  = (const float*)d_in[4];
    const float* rmean = (const float*)d_in[5];
    const float* rvar  = (const float*)d_in[6];
    float* out = (float*)d_out;

    pack_kernel<<<NA_BLOCKS + P_OUT, 256>>>(x, w, bias, gamma, beta, rmean, rvar);
    conv_kernel<<<N_IMG * 14 * 4, 224>>>(x, out);
}

// round 15
// speedup vs baseline: 1.2684x; 1.0279x over previous
#include <cuda_runtime.h>
#include <cstdint>

#define N_IMG 32
#define C_IN  128
#define H_DIM 56
#define W_DIM 56
#define P_OUT 128
#define HP (H_DIM + 2)
#define WP (W_DIM + 2)
#define BN_EPS 1e-5f
#define NA_BLOCKS (N_IMG * 15)        // pack_a blocks in the fused pack kernel
#define CSTR 132                      // global class-table stride
#define SSTR 36                       // smem class-table stride (bank spread)

// Scratch (allocation-free rule: __device__ globals)
__device__ uint4  g_apack[N_IMG * HP * WP];   // packed activations, zero border
__device__ uint4  g_wpack[P_OUT * 9];         // packed weights per tap (4 x u32)
__device__ int    g_ccls[9 * CSTR];           // per-class border corrections
__device__ float2 g_sc[P_OUT];                // (scale, offset) fused bias+BN

// full adder: sum of three bit-vectors -> sum (w1) + carry (w2). 2 LOP3s.
__device__ __forceinline__ void fa(unsigned a, unsigned b, unsigned c,
                                   unsigned &s, unsigned &cy) {
    s  = a ^ b ^ c;                       // LOP3 0x96
    cy = (a & b) | (a & c) | (b & c);     // LOP3 0xE8 (majority)
}

// 9-input CSA popcount: taps t[0..8] -> weighted popc partials (4 POPC).
__device__ __forceinline__ void popc9(const unsigned* t, int &p1, int &p2, int &p4) {
    unsigned s1a, c1a, s1b, c1b, s1c, c1c;
    fa(t[0], t[1], t[2], s1a, c1a);
    fa(t[3], t[4], t[5], s1b, c1b);
    fa(t[6], t[7], t[8], s1c, c1c);
    unsigned S1, C2a, S2, C4;
    fa(s1a, s1b, s1c, S1, C2a);     // weight 1 + weight 2
    fa(c1a, c1b, c1c, S2, C4);      // weight 2 + weight 4
    p1 += __popc(S1);
    p2 += __popc(C2a) + __popc(S2);
    p4 += __popc(C4);
}

// ---------------------------------------------------------------------------
// Fused pack kernel: blocks [0, NA_BLOCKS) pack activations, blocks
// [NA_BLOCKS, NA_BLOCKS+128) pack weights + class corrections + BN constants.
// ---------------------------------------------------------------------------
__global__ void __launch_bounds__(256)
pack_kernel(const float* __restrict__ x,
            const float* __restrict__ w,
            const float* __restrict__ bias,
            const float* __restrict__ gamma,
            const float* __restrict__ beta,
            const float* __restrict__ rmean,
            const float* __restrict__ rvar) {
    if (blockIdx.x < NA_BLOCKS) {
        int b = blockIdx.x;
        int rq = b % 15;
        int n  = b / 15;
        int hp = rq * 4 + (threadIdx.x >> 6);
        int wp = threadIdx.x & 63;
        if (hp >= HP || wp >= WP) return;

        uint4 v = make_uint4(0u, 0u, 0u, 0u);
        if (hp >= 1 && hp <= H_DIM && wp >= 1 && wp <= W_DIM) {
            int h = hp - 1, ww = wp - 1;
            const float* base = x + (size_t)n * C_IN * H_DIM * W_DIM + h * W_DIM + ww;
            unsigned int words[4] = {0u, 0u, 0u, 0u};
            #pragma unroll 8
            for (int c = 0; c < C_IN; c++) {
                float f = base[(size_t)c * H_DIM * W_DIM];
                words[c >> 5] |= (unsigned int)(f >= 0.0f) << (c & 31);
            }
            v = make_uint4(words[0], words[1], words[2], words[3]);
        }
        g_apack[(n * HP + hp) * WP + wp] = v;
    } else {
        int p = blockIdx.x - NA_BLOCKS;   // 0..127
        int c = threadIdx.x;
        int lane = c & 31, wd = c >> 5;

        __shared__ unsigned sw[9][4];
        __shared__ int ssum[9];

        if (c < 128) {
            #pragma unroll
            for (int t = 0; t < 9; t++) {
                float v = w[(size_t)(p * C_IN + c) * 9 + t];
                unsigned m = __ballot_sync(0xffffffffu, v >= 0.0f);
                if (lane == 0) sw[t][wd] = m;
            }
        }
        __syncthreads();

        if (c < 9) {
            int t = c;
            int pc = __popc(sw[t][0]) + __popc(sw[t][1]) + __popc(sw[t][2]) + __popc(sw[t][3]);
            ssum[t] = 2 * pc - C_IN;
        }
        __syncthreads();

        if (c < 9) {
            g_wpack[p * 9 + c] = make_uint4(sw[c][0], sw[c][1], sw[c][2], sw[c][3]);
        }
        if (c == 0) {
            const int* ws = ssum;
            int top = ws[0] + ws[1] + ws[2];
            int bot = ws[6] + ws[7] + ws[8];
            int lef = ws[0] + ws[3] + ws[6];
            int rig = ws[2] + ws[5] + ws[8];
            // classes: 0=interior 1=L 2=R 3=T 4=B 5=TL 6=TR 7=BL 8=BR
            g_ccls[0 * CSTR + p] = 0;
            g_ccls[1 * CSTR + p] = lef;
            g_ccls[2 * CSTR + p] = rig;
            g_ccls[3 * CSTR + p] = top;
            g_ccls[4 * CSTR + p] = bot;
            g_ccls[5 * CSTR + p] = top + lef - ws[0];
            g_ccls[6 * CSTR + p] = top + rig - ws[2];
            g_ccls[7 * CSTR + p] = bot + lef - ws[6];
            g_ccls[8 * CSTR + p] = bot + rig - ws[8];

            float inv = gamma[p] / sqrtf(rvar[p] + BN_EPS);
            float offs = bias[p] * inv + beta[p] - rmean[p] * inv;
            g_sc[p] = make_float2(inv, offs);
        }
    }
}

// ---------------------------------------------------------------------------
// Fused XNOR conv + bias + BN + residual, K-split across lane pairs.
// r14 champion geometry (224 thr, uh = t&1 channel-half, shfl_xor exchange,
// depth-2 residual prefetch, per-u2 weight loads). This round:
//   - border correction via per-thread class pointer (1 LDS + 1 IADD/iter)
//   - __launch_bounds__(224, 4): 4 CTAs/SM (<=72 regs), occ 29% -> ~39%
// ---------------------------------------------------------------------------
__global__ void __launch_bounds__(224, 4)
conv_kernel(const float* __restrict__ x, float* __restrict__ out) {
    __shared__ uint4    s_act[6 * WP];     // 5.6 KB (padded rows hp0..hp0+5)
    __shared__ unsigned s_wt[32 * 48];     // 6 KB: [ch][u-word 0..3][tap 0..8, pad 12]
    __shared__ int      s_ccls[9 * SSTR];  // 1.3 KB: per-class corrections (this cg)
    __shared__ float2   s_sc[32];

    int b = blockIdx.x;                    // ((n*14 + rblk)*4 + cg)
    int cg   = b & 3;
    int rblk = (b >> 2) % 14;
    int n    = b / 56;
    int cbase = cg * 32;
    int t = threadIdx.x;

    // stage weights: s_wt[ch*48 + u*12 + tap] = word u of tap
    for (int idx = t; idx < 32 * 9; idx += 224) {
        int i = idx / 9, tap = idx % 9;
        uint4 v = g_wpack[(cbase + i) * 9 + tap];
        s_wt[i * 48 +  0 + tap] = v.x;
        s_wt[i * 48 + 12 + tap] = v.y;
        s_wt[i * 48 + 24 + tap] = v.z;
        s_wt[i * 48 + 36 + tap] = v.w;
    }
    for (int i = t; i < 9 * 32; i += 224)
        s_ccls[(i >> 5) * SSTR + (i & 31)] = g_ccls[(i >> 5) * CSTR + cbase + (i & 31)];
    if (t < 32) s_sc[t] = g_sc[cbase + t];
    int hp0 = rblk * 4;
    for (int i = t; i < 6 * WP; i += 224)
        s_act[i] = g_apack[(n * HP + hp0 + i / WP) * WP + (i % WP)];
    __syncthreads();

    int uh = t & 1;           // channel-half (and the row this thread stores)
    int j  = t >> 1;          // 0..111
    int w  = j % 56;
    int rp = j / 56;          // row pair within the 4-row tile
    int h  = hp0 + rp * 2 + uh;   // this thread's output row

    // activation window: 4 rows x 3 cols x 2 words (this channel-half)
    unsigned xa[4][6];
    #pragma unroll
    for (int dr = 0; dr < 4; dr++) {
        #pragma unroll
        for (int dc = 0; dc < 3; dc++) {
            const unsigned* pv = (const unsigned*)&s_act[(rp * 2 + dr) * WP + w + dc];
            xa[dr][dc * 2 + 0] = pv[2 * uh + 0];
            xa[dr][dc * 2 + 1] = pv[2 * uh + 1];
        }
    }

    // border class for THIS thread's row (thread-constant)
    {
        int ft = (h == 0), fb = (h == H_DIM - 1);
        int fl = (w == 0), fr = (w == W_DIM - 1);
        int cls = ft ? (fl ? 5 : (fr ? 6 : 3))
                     : (fb ? (fl ? 7 : (fr ? 8 : 4))
                           : (fl ? 1 : (fr ? 2 : 0)));
        // fold class into a pointer; interior threads broadcast from class 0
        t = cls;                           // reuse register
    }
    const int* cc = &s_ccls[t * SSTR];

    const size_t cstride = (size_t)H_DIM * W_DIM;
    const float* xin = x   + ((size_t)(n * P_OUT + cbase) * H_DIM + h) * W_DIM + w;
    float*       ob  = out + ((size_t)(n * P_OUT + cbase) * H_DIM + h) * W_DIM + w;
    const unsigned* wb = &s_wt[uh * 24];   // u2=0 at +0, u2=1 at +12

    // depth-2 residual prefetch pipeline
    float xc = xin[0];
    float x1 = xin[cstride];

    #pragma unroll 1
    for (int i = 0; i < 32; i++) {
        int ipre = (i + 2 < 32) ? (i + 2) : 31;
        float x2 = xin[(size_t)ipre * cstride];

        int p1a = 0, p2a = 0, p4a = 0;   // pair row 0, this half
        int p1b = 0, p2b = 0, p4b = 0;   // pair row 1, this half

        #pragma unroll
        for (int u2 = 0; u2 < 2; u2++) {
            const unsigned* wp9 = wb + i * 48 + u2 * 12;
            uint4 q0 = *(const uint4*)(wp9);
            uint4 q1 = *(const uint4*)(wp9 + 4);
            unsigned w8 = wp9[8];
            unsigned wv[9] = {q0.x, q0.y, q0.z, q0.w, q1.x, q1.y, q1.z, q1.w, w8};

            unsigned ta[9], tb[9];
            #pragma unroll
            for (int tp = 0; tp < 9; tp++) {
                int dr = tp / 3, dc = tp % 3;
                ta[tp] = xa[dr    ][dc * 2 + u2] ^ wv[tp];
                tb[tp] = xa[dr + 1][dc * 2 + u2] ^ wv[tp];
            }
            popc9(ta, p1a, p2a, p4a);
            popc9(tb, p1b, p2b, p4b);
        }
        int pc0 = p1a + 2 * p2a + 4 * p4a;
        int pc1 = p1b + 2 * p2b + 4 * p4b;

        // cross-exchange: keep own row's partial, send the other row's.
        int keep = uh ? pc1 : pc0;
        int send = uh ? pc0 : pc1;
        int full = keep + __shfl_xor_sync(0xffffffffu, send, 1);

        int dot = 9 * C_IN + cc[i] - 2 * full;

        float2 sc = s_sc[i];
        ob[i * cstride] = (float)dot * sc.x + sc.y + xc;
        xc = x1;
        x1 = x2;
    }
}

// ---------------------------------------------------------------------------
extern "C" void kernel_launch(void* const* d_in, const int* in_sizes, int n_in,
                              void* d_out, int out_size) {
    const float* x     = (const float*)d_in[0];
    const float* w     = (const float*)d_in[1];
    const float* bias  = (const float*)d_in[2];
    const float* gamma = (const float*)d_in[3];
    const float* beta  = (const float*)d_in[4];
    const float* rmean = (const float*)d_in[5];
    const float* rvar  = (const float*)d_in[6];
    float* out = (float*)d_out;

    pack_kernel<<<NA_BLOCKS + P_OUT, 256>>>(x, w, bias, gamma, beta, rmean, rvar);
    conv_kernel<<<N_IMG * 14 * 4, 224>>>(x, out);
}

// round 16
// speedup vs baseline: 1.2799x; 1.0091x over previous
#include <cuda_runtime.h>
#include <cstdint>

#define N_IMG 32
#define C_IN  128
#define H_DIM 56
#define W_DIM 56
#define P_OUT 128
#define HP (H_DIM + 2)
#define WP (W_DIM + 2)
#define BN_EPS 1e-5f
#define NA_BLOCKS (N_IMG * 15)        // pack_a blocks in the fused pack kernel
#define CSTR 132                      // global class-table stride
#define FSTR 34                       // smem float2 class-table stride

// Scratch (allocation-free rule: __device__ globals)
__device__ uint4  g_apack[N_IMG * HP * WP];   // packed activations, zero border
__device__ uint4  g_wpack[P_OUT * 9];         // packed weights per tap (4 x u32)
__device__ float2 g_fc[9 * CSTR];             // per-(class,channel) folded (m, o)

// full adder: sum of three bit-vectors -> sum (w1) + carry (w2). 2 LOP3s.
__device__ __forceinline__ void fa(unsigned a, unsigned b, unsigned c,
                                   unsigned &s, unsigned &cy) {
    s  = a ^ b ^ c;                       // LOP3 0x96
    cy = (a & b) | (a & c) | (b & c);     // LOP3 0xE8 (majority)
}

// 9-input CSA popcount: taps t[0..8] -> weighted popc partials (4 POPC).
__device__ __forceinline__ void popc9(const unsigned* t, int &p1, int &p2, int &p4) {
    unsigned s1a, c1a, s1b, c1b, s1c, c1c;
    fa(t[0], t[1], t[2], s1a, c1a);
    fa(t[3], t[4], t[5], s1b, c1b);
    fa(t[6], t[7], t[8], s1c, c1c);
    unsigned S1, C2a, S2, C4;
    fa(s1a, s1b, s1c, S1, C2a);     // weight 1 + weight 2
    fa(c1a, c1b, c1c, S2, C4);      // weight 2 + weight 4
    p1 += __popc(S1);
    p2 += __popc(C2a) + __popc(S2);
    p4 += __popc(C4);
}

// ---------------------------------------------------------------------------
// Fused pack kernel: blocks [0, NA_BLOCKS) pack activations, blocks
// [NA_BLOCKS, NA_BLOCKS+128) pack weights + folded epilogue constants.
// ---------------------------------------------------------------------------
__global__ void __launch_bounds__(256)
pack_kernel(const float* __restrict__ x,
            const float* __restrict__ w,
            const float* __restrict__ bias,
            const float* __restrict__ gamma,
            const float* __restrict__ beta,
            const float* __restrict__ rmean,
            const float* __restrict__ rvar) {
    if (blockIdx.x < NA_BLOCKS) {
        int b = blockIdx.x;
        int rq = b % 15;
        int n  = b / 15;
        int hp = rq * 4 + (threadIdx.x >> 6);
        int wp = threadIdx.x & 63;
        if (hp >= HP || wp >= WP) return;

        uint4 v = make_uint4(0u, 0u, 0u, 0u);
        if (hp >= 1 && hp <= H_DIM && wp >= 1 && wp <= W_DIM) {
            int h = hp - 1, ww = wp - 1;
            const float* base = x + (size_t)n * C_IN * H_DIM * W_DIM + h * W_DIM + ww;
            unsigned int words[4] = {0u, 0u, 0u, 0u};
            #pragma unroll 8
            for (int c = 0; c < C_IN; c++) {
                float f = base[(size_t)c * H_DIM * W_DIM];
                words[c >> 5] |= (unsigned int)(f >= 0.0f) << (c & 31);
            }
            v = make_uint4(words[0], words[1], words[2], words[3]);
        }
        g_apack[(n * HP + hp) * WP + wp] = v;
    } else {
        int p = blockIdx.x - NA_BLOCKS;   // 0..127
        int c = threadIdx.x;
        int lane = c & 31, wd = c >> 5;

        __shared__ unsigned sw[9][4];
        __shared__ int ssum[9];

        if (c < 128) {
            #pragma unroll
            for (int t = 0; t < 9; t++) {
                float v = w[(size_t)(p * C_IN + c) * 9 + t];
                unsigned m = __ballot_sync(0xffffffffu, v >= 0.0f);
                if (lane == 0) sw[t][wd] = m;
            }
        }
        __syncthreads();

        if (c < 9) {
            int t = c;
            int pc = __popc(sw[t][0]) + __popc(sw[t][1]) + __popc(sw[t][2]) + __popc(sw[t][3]);
            ssum[t] = 2 * pc - C_IN;
        }
        __syncthreads();

        if (c < 9) {
            g_wpack[p * 9 + c] = make_uint4(sw[c][0], sw[c][1], sw[c][2], sw[c][3]);
        }
        if (c == 0) {
            const int* ws = ssum;
            int top = ws[0] + ws[1] + ws[2];
            int bot = ws[6] + ws[7] + ws[8];
            int lef = ws[0] + ws[3] + ws[6];
            int rig = ws[2] + ws[5] + ws[8];
            int cc[9];
            cc[0] = 0;                    // interior
            cc[1] = lef;  cc[2] = rig;    // L, R
            cc[3] = top;  cc[4] = bot;    // T, B
            cc[5] = top + lef - ws[0];    // TL
            cc[6] = top + rig - ws[2];    // TR
            cc[7] = bot + lef - ws[6];    // BL
            cc[8] = bot + rig - ws[8];    // BR

            float inv  = gamma[p] / sqrtf(rvar[p] + BN_EPS);
            float offs = bias[p] * inv + beta[p] - rmean[p] * inv;
            float m    = -2.0f * inv;
            #pragma unroll
            for (int cls = 0; cls < 9; cls++) {
                float o = (float)(9 * C_IN + cc[cls]) * inv + offs;
                g_fc[cls * CSTR + p] = make_float2(m, o);
            }
        }
    }
}

// ---------------------------------------------------------------------------
// Fused XNOR conv + bias + BN + residual, K-split across lane pairs.
// r15 champion geometry (224 thr, uh = t&1 channel-half, shfl_xor exchange,
// depth-2 residual prefetch, 4 CTAs/SM). This round: folded float epilogue
// (FFMA(full, m, o) + x, one LDS.64) and paired tap-8 weights (one LDS.64).
// ---------------------------------------------------------------------------
__global__ void __launch_bounds__(224, 4)
conv_kernel(const float* __restrict__ x, float* __restrict__ out) {
    __shared__ uint4    s_act[6 * WP];     // 5.6 KB (padded rows hp0..hp0+5)
    __shared__ unsigned s_wt[32 * 32];     // 4 KB: [ch][u 0..3][tap 0..7]
    __shared__ uint2    s_w8[32 * 2];      // 512 B: [ch][uh] = (tap8_u0, tap8_u1)
    __shared__ float2   s_fc[9 * FSTR];    // 2.4 KB: per-class folded (m, o)

    int b = blockIdx.x;                    // ((n*14 + rblk)*4 + cg)
    int cg   = b & 3;
    int rblk = (b >> 2) % 14;
    int n    = b / 56;
    int cbase = cg * 32;
    int t = threadIdx.x;

    // stage weights: taps 0..7 -> s_wt[ch*32 + u*8 + tap]; tap 8 -> s_w8
    for (int idx = t; idx < 32 * 9; idx += 224) {
        int i = idx / 9, tap = idx % 9;
        uint4 v = g_wpack[(cbase + i) * 9 + tap];
        if (tap < 8) {
            s_wt[i * 32 +  0 + tap] = v.x;
            s_wt[i * 32 +  8 + tap] = v.y;
            s_wt[i * 32 + 16 + tap] = v.z;
            s_wt[i * 32 + 24 + tap] = v.w;
        } else {
            s_w8[i * 2 + 0] = make_uint2(v.x, v.y);
            s_w8[i * 2 + 1] = make_uint2(v.z, v.w);
        }
    }
    for (int i = t; i < 9 * 32; i += 224)
        s_fc[(i >> 5) * FSTR + (i & 31)] = g_fc[(i >> 5) * CSTR + cbase + (i & 31)];
    int hp0 = rblk * 4;
    for (int i = t; i < 6 * WP; i += 224)
        s_act[i] = g_apack[(n * HP + hp0 + i / WP) * WP + (i % WP)];
    __syncthreads();

    int uh = t & 1;           // channel-half (and the row this thread stores)
    int j  = t >> 1;          // 0..111
    int w  = j % 56;
    int rp = j / 56;          // row pair within the 4-row tile
    int h  = hp0 + rp * 2 + uh;   // this thread's output row

    // activation window: 4 rows x 3 cols x 2 words (this channel-half)
    unsigned xa[4][6];
    #pragma unroll
    for (int dr = 0; dr < 4; dr++) {
        #pragma unroll
        for (int dc = 0; dc < 3; dc++) {
            const unsigned* pv = (const unsigned*)&s_act[(rp * 2 + dr) * WP + w + dc];
            xa[dr][dc * 2 + 0] = pv[2 * uh + 0];
            xa[dr][dc * 2 + 1] = pv[2 * uh + 1];
        }
    }

    // border class for THIS thread's row (thread-constant)
    {
        int ft = (h == 0), fb = (h == H_DIM - 1);
        int fl = (w == 0), fr = (w == W_DIM - 1);
        int cls = ft ? (fl ? 5 : (fr ? 6 : 3))
                     : (fb ? (fl ? 7 : (fr ? 8 : 4))
                           : (fl ? 1 : (fr ? 2 : 0)));
        t = cls;                           // reuse register
    }
    const float2* fcb = &s_fc[t * FSTR];

    const size_t cstride = (size_t)H_DIM * W_DIM;
    const float* xin = x   + ((size_t)(n * P_OUT + cbase) * H_DIM + h) * W_DIM + w;
    float*       ob  = out + ((size_t)(n * P_OUT + cbase) * H_DIM + h) * W_DIM + w;
    const unsigned* wb = &s_wt[uh * 16];   // u2=0 at +0..7, u2=1 at +8..15
    const uint2*    w8b = &s_w8[uh];

    // depth-2 residual prefetch pipeline
    float xc = xin[0];
    float x1 = xin[cstride];

    #pragma unroll 1
    for (int i = 0; i < 32; i++) {
        int ipre = (i + 2 < 32) ? (i + 2) : 31;
        float x2 = xin[(size_t)ipre * cstride];

        uint2 w8p = w8b[i * 2];          // tap8 words for u2 = 0 / 1

        int p1a = 0, p2a = 0, p4a = 0;   // pair row 0, this half
        int p1b = 0, p2b = 0, p4b = 0;   // pair row 1, this half

        #pragma unroll
        for (int u2 = 0; u2 < 2; u2++) {
            const unsigned* wp8 = wb + i * 32 + u2 * 8;
            uint4 q0 = *(const uint4*)(wp8);
            uint4 q1 = *(const uint4*)(wp8 + 4);
            unsigned w8 = u2 ? w8p.y : w8p.x;
            unsigned wv[9] = {q0.x, q0.y, q0.z, q0.w, q1.x, q1.y, q1.z, q1.w, w8};

            unsigned ta[9], tb[9];
            #pragma unroll
            for (int tp = 0; tp < 9; tp++) {
                int dr = tp / 3, dc = tp % 3;
                ta[tp] = xa[dr    ][dc * 2 + u2] ^ wv[tp];
                tb[tp] = xa[dr + 1][dc * 2 + u2] ^ wv[tp];
            }
            popc9(ta, p1a, p2a, p4a);
            popc9(tb, p1b, p2b, p4b);
        }
        int pc0 = p1a + 2 * p2a + 4 * p4a;
        int pc1 = p1b + 2 * p2b + 4 * p4b;

        // cross-exchange: keep own row's partial, send the other row's.
        int keep = uh ? pc1 : pc0;
        int send = uh ? pc0 : pc1;
        int full = keep + __shfl_xor_sync(0xffffffffu, send, 1);

        float2 fc = fcb[i];
        ob[i * cstride] = fmaf((float)full, fc.x, fc.y) + xc;
        xc = x1;
        x1 = x2;
    }
}

// ---------------------------------------------------------------------------
extern "C" void kernel_launch(void* const* d_in, const int* in_sizes, int n_in,
                              void* d_out, int out_size) {
    const float* x     = (const float*)d_in[0];
    const float* w     = (const float*)d_in[1];
    const float* bias  = (const float*)d_in[2];
    const float* gamma = (const float*)d_in[3];
    const float* beta  = (const float*)d_in[4];
    const float* rmean = (const float*)d_in[5];
    const float* rvar  = (const float*)d_in[6];
    float* out = (float*)d_out;

    pack_kernel<<<NA_BLOCKS + P_OUT, 256>>>(x, w, bias, gamma, beta, rmean, rvar);
    conv_kernel<<<N_IMG * 14 * 4, 224>>>(x, out);
}

// round 17
// speedup vs baseline: 1.3295x; 1.0387x over previous
#include <cuda_runtime.h>
#include <cstdint>

#define N_IMG 32
#define C_IN  128
#define H_DIM 56
#define W_DIM 56
#define P_OUT 128
#define HP (H_DIM + 2)
#define WP (W_DIM + 2)
#define BN_EPS 1e-5f
#define NA_BLOCKS (N_IMG * 15)        // pack_a blocks in the fused pack kernel
#define CSTR 132                      // global class-table stride
#define FSTR 34                       // smem float2 class-table stride

// Scratch (allocation-free rule: __device__ globals)
__device__ uint4  g_apack[N_IMG * HP * WP];   // packed activations, zero border
__device__ uint4  g_wpack[P_OUT * 9];         // packed weights per tap (4 x u32)
__device__ float2 g_fc[9 * CSTR];             // per-(class,channel) folded (m, o)

// full adder: sum of three bit-vectors -> sum (w1) + carry (w2). 2 LOP3s.
__device__ __forceinline__ void fa(unsigned a, unsigned b, unsigned c,
                                   unsigned &s, unsigned &cy) {
    s  = a ^ b ^ c;                       // LOP3 0x96
    cy = (a & b) | (a & c) | (b & c);     // LOP3 0xE8 (majority)
}

// accumulate on the FMA pipe: acc += v * one  (one is runtime-opaque == 1,
// so ptxas emits IMAD -> fma pipe instead of IADD3 -> alu pipe)
__device__ __forceinline__ void madacc(int &acc, int v, int one) {
    asm("mad.lo.s32 %0, %1, %2, %0;" : "+r"(acc) : "r"(v), "r"(one));
}

// 9-input CSA popcount: taps t[0..8] -> weighted popc partials (4 POPC,
// accumulation offloaded to the fma pipe via madacc).
__device__ __forceinline__ void popc9(const unsigned* t, int &p1, int &p2, int &p4,
                                      int one) {
    unsigned s1a, c1a, s1b, c1b, s1c, c1c;
    fa(t[0], t[1], t[2], s1a, c1a);
    fa(t[3], t[4], t[5], s1b, c1b);
    fa(t[6], t[7], t[8], s1c, c1c);
    unsigned S1, C2a, S2, C4;
    fa(s1a, s1b, s1c, S1, C2a);     // weight 1 + weight 2
    fa(c1a, c1b, c1c, S2, C4);      // weight 2 + weight 4
    madacc(p1, __popc(S1), one);
    madacc(p2, __popc(C2a), one);
    madacc(p2, __popc(S2), one);
    madacc(p4, __popc(C4), one);
}

// ---------------------------------------------------------------------------
// Fused pack kernel: blocks [0, NA_BLOCKS) pack activations, blocks
// [NA_BLOCKS, NA_BLOCKS+128) pack weights + folded epilogue constants.
// ---------------------------------------------------------------------------
__global__ void __launch_bounds__(256)
pack_kernel(const float* __restrict__ x,
            const float* __restrict__ w,
            const float* __restrict__ bias,
            const float* __restrict__ gamma,
            const float* __restrict__ beta,
            const float* __restrict__ rmean,
            const float* __restrict__ rvar) {
    if (blockIdx.x < NA_BLOCKS) {
        int b = blockIdx.x;
        int rq = b % 15;
        int n  = b / 15;
        int hp = rq * 4 + (threadIdx.x >> 6);
        int wp = threadIdx.x & 63;
        if (hp >= HP || wp >= WP) return;

        uint4 v = make_uint4(0u, 0u, 0u, 0u);
        if (hp >= 1 && hp <= H_DIM && wp >= 1 && wp <= W_DIM) {
            int h = hp - 1, ww = wp - 1;
            const unsigned* base = (const unsigned*)(x
                + (size_t)n * C_IN * H_DIM * W_DIM + h * W_DIM + ww);
            unsigned int words[4] = {0u, 0u, 0u, 0u};
            // sign-shift bit build: 2 alu ops per element (SHF + LOP3),
            // bit set when float is non-negative (sign bit clear)
            #pragma unroll
            for (int c = 0; c < C_IN; c++) {
                unsigned u = base[(size_t)c * H_DIM * W_DIM];
                unsigned s = (unsigned)((int)u >> 31);    // all-ones if negative
                words[c >> 5] |= ~s & (1u << (c & 31));
            }
            v = make_uint4(words[0], words[1], words[2], words[3]);
        }
        g_apack[(n * HP + hp) * WP + wp] = v;
    } else {
        int p = blockIdx.x - NA_BLOCKS;   // 0..127
        int c = threadIdx.x;
        int lane = c & 31, wd = c >> 5;

        __shared__ unsigned sw[9][4];
        __shared__ int ssum[9];

        if (c < 128) {
            #pragma unroll
            for (int t = 0; t < 9; t++) {
                float v = w[(size_t)(p * C_IN + c) * 9 + t];
                unsigned m = __ballot_sync(0xffffffffu, v >= 0.0f);
                if (lane == 0) sw[t][wd] = m;
            }
        }
        __syncthreads();

        if (c < 9) {
            int t = c;
            int pc = __popc(sw[t][0]) + __popc(sw[t][1]) + __popc(sw[t][2]) + __popc(sw[t][3]);
            ssum[t] = 2 * pc - C_IN;
        }
        __syncthreads();

        if (c < 9) {
            g_wpack[p * 9 + c] = make_uint4(sw[c][0], sw[c][1], sw[c][2], sw[c][3]);
        }
        if (c == 0) {
            const int* ws = ssum;
            int top = ws[0] + ws[1] + ws[2];
            int bot = ws[6] + ws[7] + ws[8];
            int lef = ws[0] + ws[3] + ws[6];
            int rig = ws[2] + ws[5] + ws[8];
            int cc[9];
            cc[0] = 0;                    // interior
            cc[1] = lef;  cc[2] = rig;    // L, R
            cc[3] = top;  cc[4] = bot;    // T, B
            cc[5] = top + lef - ws[0];    // TL
            cc[6] = top + rig - ws[2];    // TR
            cc[7] = bot + lef - ws[6];    // BL
            cc[8] = bot + rig - ws[8];    // BR

            float inv  = gamma[p] / sqrtf(rvar[p] + BN_EPS);
            float offs = bias[p] * inv + beta[p] - rmean[p] * inv;
            float m    = -2.0f * inv;
            #pragma unroll
            for (int cls = 0; cls < 9; cls++) {
                float o = (float)(9 * C_IN + cc[cls]) * inv + offs;
                g_fc[cls * CSTR + p] = make_float2(m, o);
            }
        }
    }
}

// ---------------------------------------------------------------------------
// Fused XNOR conv + bias + BN + residual, K-split across lane pairs.
// r16 champion geometry (224 thr, uh = t&1 channel-half, shfl_xor exchange,
// depth-2 residual prefetch, 4 CTAs/SM, folded FFMA epilogue). This round:
// popcount accumulation moved to the idle FMA pipe via opaque-one IMAD.
// ---------------------------------------------------------------------------
__global__ void __launch_bounds__(224, 4)
conv_kernel(const float* __restrict__ x, float* __restrict__ out) {
    __shared__ uint4    s_act[6 * WP];     // 5.6 KB (padded rows hp0..hp0+5)
    __shared__ unsigned s_wt[32 * 32];     // 4 KB: [ch][u 0..3][tap 0..7]
    __shared__ uint2    s_w8[32 * 2];      // 512 B: [ch][uh] = (tap8_u0, tap8_u1)
    __shared__ float2   s_fc[9 * FSTR];    // 2.4 KB: per-class folded (m, o)

    int b = blockIdx.x;                    // ((n*14 + rblk)*4 + cg)
    int cg   = b & 3;
    int rblk = (b >> 2) % 14;
    int n    = b / 56;
    int cbase = cg * 32;
    int t = threadIdx.x;

    // runtime-opaque 1 (blockDim.x = 224 -> high bits are 0)
    int one = 1 + (int)(blockDim.x >> 16);

    // stage weights: taps 0..7 -> s_wt[ch*32 + u*8 + tap]; tap 8 -> s_w8
    for (int idx = t; idx < 32 * 9; idx += 224) {
        int i = idx / 9, tap = idx % 9;
        uint4 v = g_wpack[(cbase + i) * 9 + tap];
        if (tap < 8) {
            s_wt[i * 32 +  0 + tap] = v.x;
            s_wt[i * 32 +  8 + tap] = v.y;
            s_wt[i * 32 + 16 + tap] = v.z;
            s_wt[i * 32 + 24 + tap] = v.w;
        } else {
            s_w8[i * 2 + 0] = make_uint2(v.x, v.y);
            s_w8[i * 2 + 1] = make_uint2(v.z, v.w);
        }
    }
    for (int i = t; i < 9 * 32; i += 224)
        s_fc[(i >> 5) * FSTR + (i & 31)] = g_fc[(i >> 5) * CSTR + cbase + (i & 31)];
    int hp0 = rblk * 4;
    for (int i = t; i < 6 * WP; i += 224)
        s_act[i] = g_apack[(n * HP + hp0 + i / WP) * WP + (i % WP)];
    __syncthreads();

    int uh = t & 1;           // channel-half (and the row this thread stores)
    int j  = t >> 1;          // 0..111
    int w  = j % 56;
    int rp = j / 56;          // row pair within the 4-row tile
    int h  = hp0 + rp * 2 + uh;   // this thread's output row

    // activation window: 4 rows x 3 cols x 2 words (this channel-half)
    unsigned xa[4][6];
    #pragma unroll
    for (int dr = 0; dr < 4; dr++) {
        #pragma unroll
        for (int dc = 0; dc < 3; dc++) {
            const unsigned* pv = (const unsigned*)&s_act[(rp * 2 + dr) * WP + w + dc];
            xa[dr][dc * 2 + 0] = pv[2 * uh + 0];
            xa[dr][dc * 2 + 1] = pv[2 * uh + 1];
        }
    }

    // border class for THIS thread's row (thread-constant)
    {
        int ft = (h == 0), fb = (h == H_DIM - 1);
        int fl = (w == 0), fr = (w == W_DIM - 1);
        int cls = ft ? (fl ? 5 : (fr ? 6 : 3))
                     : (fb ? (fl ? 7 : (fr ? 8 : 4))
                           : (fl ? 1 : (fr ? 2 : 0)));
        t = cls;                           // reuse register
    }
    const float2* fcb = &s_fc[t * FSTR];

    const size_t cstride = (size_t)H_DIM * W_DIM;
    const float* xin = x   + ((size_t)(n * P_OUT + cbase) * H_DIM + h) * W_DIM + w;
    float*       ob  = out + ((size_t)(n * P_OUT + cbase) * H_DIM + h) * W_DIM + w;
    const unsigned* wb = &s_wt[uh * 16];   // u2=0 at +0..7, u2=1 at +8..15
    const uint2*    w8b = &s_w8[uh];

    // depth-2 residual prefetch pipeline
    float xc = xin[0];
    float x1 = xin[cstride];

    #pragma unroll 1
    for (int i = 0; i < 32; i++) {
        int ipre = (i + 2 < 32) ? (i + 2) : 31;
        float x2 = xin[(size_t)ipre * cstride];

        uint2 w8p = w8b[i * 2];          // tap8 words for u2 = 0 / 1

        int p1a = 0, p2a = 0, p4a = 0;   // pair row 0, this half
        int p1b = 0, p2b = 0, p4b = 0;   // pair row 1, this half

        #pragma unroll
        for (int u2 = 0; u2 < 2; u2++) {
            const unsigned* wp8 = wb + i * 32 + u2 * 8;
            uint4 q0 = *(const uint4*)(wp8);
            uint4 q1 = *(const uint4*)(wp8 + 4);
            unsigned w8 = u2 ? w8p.y : w8p.x;
            unsigned wv[9] = {q0.x, q0.y, q0.z, q0.w, q1.x, q1.y, q1.z, q1.w, w8};

            unsigned ta[9], tb[9];
            #pragma unroll
            for (int tp = 0; tp < 9; tp++) {
                int dr = tp / 3, dc = tp % 3;
                ta[tp] = xa[dr    ][dc * 2 + u2] ^ wv[tp];
                tb[tp] = xa[dr + 1][dc * 2 + u2] ^ wv[tp];
            }
            popc9(ta, p1a, p2a, p4a, one);
            popc9(tb, p1b, p2b, p4b, one);
        }
        // weighted combine on the fma pipe as well
        int pc0 = p1a, pc1 = p1b;
        madacc(pc0, p2a, 2 * one);
        madacc(pc0, p4a, 4 * one);
        madacc(pc1, p2b, 2 * one);
        madacc(pc1, p4b, 4 * one);

        // cross-exchange: keep own row's partial, send the other row's.
        int keep = uh ? pc1 : pc0;
        int send = uh ? pc0 : pc1;
        int full = keep + __shfl_xor_sync(0xffffffffu, send, 1);

        float2 fc = fcb[i];
        ob[i * cstride] = fmaf((float)full, fc.x, fc.y) + xc;
        xc = x1;
        x1 = x2;
    }
}

// ---------------------------------------------------------------------------
extern "C" void kernel_launch(void* const* d_in, const int* in_sizes, int n_in,
                              void* d_out, int out_size) {
    const float* x     = (const float*)d_in[0];
    const float* w     = (const float*)d_in[1];
    const float* bias  = (const float*)d_in[2];
    const float* gamma = (const float*)d_in[3];
    const float* beta  = (const float*)d_in[4];
    const float* rmean = (const float*)d_in[5];
    const float* rvar  = (const float*)d_in[6];
    float* out = (float*)d_out;

    pack_kernel<<<NA_BLOCKS + P_OUT, 256>>>(x, w, bias, gamma, beta, rmean, rvar);
    conv_kernel<<<N_IMG * 14 * 4, 224>>>(x, out);
}